// round 6
// baseline (speedup 1.0000x reference)
#include <cuda_runtime.h>
#include <math.h>

#define NB 256      // batch N
#define TT 1000     // attention length T
#define KD 128      // KS
#define VD 128      // VS
#define ED 256      // EMB
#define HD 512      // HID
#define ML 250      // MAXLEN
#define VOC 30
#define NCTA 256
#define NTHR 256

// ---------------- scratch (device globals: allocation-free) ----------------
__device__ __align__(16) float g_embs[(size_t)ML*NB*ED];   // (t,n,e)
__device__ __align__(16) float g_h1[2][NB*HD];
__device__ __align__(16) float g_h2[2][NB*HD];
__device__ __align__(16) float g_h3[2][NB*KD];
__device__ __align__(16) float g_c1[NB*HD];
__device__ __align__(16) float g_c2[NB*HD];
__device__ __align__(16) float g_c3[NB*KD];
__device__ __align__(16) float g_ctx[NB*VD];
__device__ __align__(16) float g_linWT[(KD+VD)*KD];        // [k][j]
__device__ unsigned g_bar;   // zero-initialized at module load; protocol restores 0
__device__ unsigned g_gen;

// ---------------- software grid barrier (launch-invariant) ----------------
__device__ __forceinline__ void gridbar() {
    __syncthreads();
    if (threadIdx.x == 0) {
        unsigned snap = *(volatile unsigned*)&g_gen;
        __threadfence();                       // release my CTA's writes
        unsigned a = atomicAdd(&g_bar, 1u);
        if (a == NCTA - 1u) {
            g_bar = 0u;
            __threadfence();
            atomicAdd(&g_gen, 1u);
        } else {
            while (*(volatile unsigned*)&g_gen == snap) __nanosleep(64);
        }
        __threadfence();                       // acquire (L1 invalidate)
    }
    __syncthreads();
}

// ---------------- packed fp32x2 helpers ----------------
__device__ __forceinline__ unsigned long long packdup(float x) {
    unsigned long long r;
    asm("mov.b64 %0, {%1, %1};" : "=l"(r) : "r"(__float_as_uint(x)));
    return r;
}
__device__ __forceinline__ void ffma2(unsigned long long& d,
                                      unsigned long long a, unsigned long long b) {
    asm("fma.rn.f32x2 %0, %1, %2, %0;" : "+l"(d) : "l"(a), "l"(b));
}
__device__ __forceinline__ float2 unpack2(unsigned long long v) {
    unsigned lo, hi;
    asm("mov.b64 {%0, %1}, %2;" : "=r"(lo), "=r"(hi) : "l"(v));
    float2 f; f.x = __uint_as_float(lo); f.y = __uint_as_float(hi);
    return f;
}
__device__ __forceinline__ float sigf(float x) { return 1.f/(1.f + expf(-x)); }

struct Seg { const float* A; int lda; const float* W; int ldw; int K; };

// ---------------- LSTM phase: 4-gate fused GEMM + cell, BM=32 BN=32, Hout=512 ----
// smem: As padded stride 36 (32x32 tile), Ws stride 36 (4*32 k-rows x 32 j)
__device__ void lstm_big(const Seg* segs, int nseg,
                         const float* __restrict__ b_ih, const float* __restrict__ b_hh,
                         float* __restrict__ c, float* __restrict__ hnew,
                         float* s_mem)
{
    const int cta = blockIdx.x;
    if (cta >= 128) return;                     // 8 m-tiles x 16 j-tiles
    const int tid = threadIdx.x;
    const int Hout = HD;
    const int m0 = (cta >> 4) * 32;
    const int j0 = (cta & 15) * 32;
    float* As = s_mem;            // 32 k x 32 m, stride 36 -> 1152 floats
    float* Ws = s_mem + 1152;     // 128 k-rows x 32 j, stride 36 -> 4608 floats
    const int tx = tid & 15;      // j pair
    const int ty = tid >> 4;      // m pair
    unsigned long long acc2[4][2];
    #pragma unroll
    for (int g = 0; g < 4; ++g) { acc2[g][0] = 0ull; acc2[g][1] = 0ull; }

    for (int s = 0; s < nseg; ++s) {
        const float* A = segs[s].A; const float* W = segs[s].W;
        const int lda = segs[s].lda, ldw = segs[s].ldw, K = segs[s].K;
        for (int kb = 0; kb < K; kb += 32) {
            {   // A tile: 1024 floats, 1 float4/thread, stored transposed [k][m]
                int e = tid * 4;
                int row = e >> 5, col = e & 31;
                float4 v = *(const float4*)(A + (size_t)(m0+row)*lda + kb + col);
                As[(col+0)*36 + row] = v.x;
                As[(col+1)*36 + row] = v.y;
                As[(col+2)*36 + row] = v.z;
                As[(col+3)*36 + row] = v.w;
            }
            #pragma unroll
            for (int it = 0; it < 4; ++it) {    // W tiles: 4096 floats
                int e = (tid + it*256) * 4;
                int r = e >> 5, col = e & 31;
                int g = r >> 5, j = r & 31;
                float4 v = *(const float4*)(W + (size_t)(g*Hout + j0 + j)*ldw + kb + col);
                Ws[((g<<5) + col+0)*36 + j] = v.x;
                Ws[((g<<5) + col+1)*36 + j] = v.y;
                Ws[((g<<5) + col+2)*36 + j] = v.z;
                Ws[((g<<5) + col+3)*36 + j] = v.w;
            }
            __syncthreads();
            #pragma unroll
            for (int k = 0; k < 32; ++k) {
                float2 av = *(const float2*)&As[k*36 + ty*2];
                unsigned long long aa0 = packdup(av.x);
                unsigned long long aa1 = packdup(av.y);
                #pragma unroll
                for (int g = 0; g < 4; ++g) {
                    unsigned long long w2 =
                        *(const unsigned long long*)&Ws[((g<<5)+k)*36 + tx*2];
                    ffma2(acc2[g][0], w2, aa0);
                    ffma2(acc2[g][1], w2, aa1);
                }
            }
            __syncthreads();
        }
    }
    // fused cell epilogue
    #pragma unroll
    for (int i = 0; i < 2; ++i) {
        int m = m0 + ty*2 + i;
        float2 gi = unpack2(acc2[0][i]);
        float2 gf = unpack2(acc2[1][i]);
        float2 gg = unpack2(acc2[2][i]);
        float2 go = unpack2(acc2[3][i]);
        float gia[2] = {gi.x, gi.y}, gfa[2] = {gf.x, gf.y};
        float gga[2] = {gg.x, gg.y}, goa[2] = {go.x, go.y};
        #pragma unroll
        for (int jj = 0; jj < 2; ++jj) {
            int j = j0 + tx*2 + jj;
            float xi = gia[jj] + b_ih[0*HD + j] + b_hh[0*HD + j];
            float xf = gfa[jj] + b_ih[1*HD + j] + b_hh[1*HD + j];
            float xg = gga[jj] + b_ih[2*HD + j] + b_hh[2*HD + j];
            float xo = goa[jj] + b_ih[3*HD + j] + b_hh[3*HD + j];
            size_t idx = (size_t)m*HD + j;
            float cn = sigf(xf)*c[idx] + sigf(xi)*tanhf(xg);
            c[idx] = cn;
            hnew[idx] = sigf(xo)*tanhf(cn);
        }
    }
}

// ---------------- LSTM3 phase: BM=16 BN=16, Hout=128 ----------------
__device__ void lstm_small(const Seg* segs, int nseg,
                           const float* __restrict__ b_ih, const float* __restrict__ b_hh,
                           float* __restrict__ c, float* __restrict__ hnew,
                           float* s_mem)
{
    const int cta = blockIdx.x;
    if (cta >= 128) return;                     // 16 m-tiles x 8 j-tiles
    const int tid = threadIdx.x;
    const int Hout = KD;
    const int m0 = (cta >> 3) * 16;
    const int j0 = (cta & 7) * 16;
    float* As = s_mem;            // 32 k x 16 m, stride 36
    float* Ws = s_mem + 1152;     // 128 k-rows x 16 j, stride 20 -> 2560 floats
    const int tx = tid & 15;
    const int ty = tid >> 4;
    float acc[4] = {0.f, 0.f, 0.f, 0.f};

    for (int s = 0; s < nseg; ++s) {
        const float* A = segs[s].A; const float* W = segs[s].W;
        const int lda = segs[s].lda, ldw = segs[s].ldw, K = segs[s].K;
        for (int kb = 0; kb < K; kb += 32) {
            if (tid < 128) {                    // A tile: 512 floats
                int e = tid * 4;
                int row = e >> 5, col = e & 31;
                float4 v = *(const float4*)(A + (size_t)(m0+row)*lda + kb + col);
                As[(col+0)*36 + row] = v.x;
                As[(col+1)*36 + row] = v.y;
                As[(col+2)*36 + row] = v.z;
                As[(col+3)*36 + row] = v.w;
            }
            #pragma unroll
            for (int it = 0; it < 2; ++it) {    // W tiles: 2048 floats
                int e = (tid + it*256) * 4;
                int r = e >> 5, col = e & 31;
                int g = r >> 4, j = r & 15;
                float4 v = *(const float4*)(W + (size_t)(g*Hout + j0 + j)*ldw + kb + col);
                Ws[((g<<5) + col+0)*20 + j] = v.x;
                Ws[((g<<5) + col+1)*20 + j] = v.y;
                Ws[((g<<5) + col+2)*20 + j] = v.z;
                Ws[((g<<5) + col+3)*20 + j] = v.w;
            }
            __syncthreads();
            #pragma unroll
            for (int k = 0; k < 32; ++k) {
                float a = As[k*36 + ty];
                #pragma unroll
                for (int g = 0; g < 4; ++g)
                    acc[g] += Ws[((g<<5)+k)*20 + tx] * a;
            }
            __syncthreads();
        }
    }
    {
        int m = m0 + ty, j = j0 + tx;
        float xi = acc[0] + b_ih[0*KD + j] + b_hh[0*KD + j];
        float xf = acc[1] + b_ih[1*KD + j] + b_hh[1*KD + j];
        float xg = acc[2] + b_ih[2*KD + j] + b_hh[2*KD + j];
        float xo = acc[3] + b_ih[3*KD + j] + b_hh[3*KD + j];
        size_t idx = (size_t)m*KD + j;
        float cn = sigf(xf)*c[idx] + sigf(xi)*tanhf(xg);
        c[idx] = cn;
        hnew[idx] = sigf(xo)*tanhf(cn);
    }
}

// ---------------- attention + output head: one CTA per n ----------------
__device__ void attn_phase(const int* __restrict__ seqlen,
                           const float* __restrict__ keys,
                           const float* __restrict__ values,
                           const float* __restrict__ lin_b,
                           const float* __restrict__ charW,
                           const float* __restrict__ charb,
                           const float* __restrict__ h3,
                           float* __restrict__ preds,
                           float* __restrict__ attns,
                           int t, float* s_mem)
{
    float* h3s  = s_mem;          // 128
    float* es   = s_mem + 128;    // 1000
    float* ctxp = s_mem + 1128;   // 8*128
    float* ctxv = s_mem + 2152;   // 128
    float* mids = s_mem + 2280;   // 128
    float* red  = s_mem + 2408;   // 8

    int n = blockIdx.x;
    int tid = threadIdx.x;
    int w = tid >> 5, l = tid & 31;

    if (tid < KD) h3s[tid] = h3[n*KD + tid];
    int len = seqlen[n];
    if (len < 1) len = 1; if (len > TT) len = TT;
    __syncthreads();

    // energies: only tau < len read
    {
        int g = l >> 3, kq = l & 7;
        const float4* h34 = (const float4*)h3s;
        float4 hv[4];
        #pragma unroll
        for (int q = 0; q < 4; ++q) hv[q] = h34[kq + (q<<3)];
        int nIt = (len + 31) >> 5;
        for (int it = 0; it < nIt; ++it) {
            int tau = (it << 5) + (w << 2) + g;
            float p = 0.f;
            if (tau < len) {
                const float4* kp = (const float4*)(keys + ((size_t)tau*NB + n)*KD);
                #pragma unroll
                for (int q = 0; q < 4; ++q) {
                    float4 kv = kp[kq + (q<<3)];
                    p += kv.x*hv[q].x + kv.y*hv[q].y + kv.z*hv[q].z + kv.w*hv[q].w;
                }
            }
            p += __shfl_xor_sync(0xffffffffu, p, 4);
            p += __shfl_xor_sync(0xffffffffu, p, 2);
            p += __shfl_xor_sync(0xffffffffu, p, 1);
            if (kq == 0 && tau < len) es[tau] = p;
        }
    }
    __syncthreads();

    // masked softmax over TT
    float lm = -3.4e38f;
    for (int tau = tid; tau < TT; tau += NTHR) {
        float x = (tau < len) ? es[tau] : -1e9f;
        es[tau] = x;
        lm = fmaxf(lm, x);
    }
    #pragma unroll
    for (int o = 16; o; o >>= 1) lm = fmaxf(lm, __shfl_xor_sync(0xffffffffu, lm, o));
    if (l == 0) red[w] = lm;
    __syncthreads();
    float bm = fmaxf(fmaxf(fmaxf(red[0],red[1]), fmaxf(red[2],red[3])),
                     fmaxf(fmaxf(red[4],red[5]), fmaxf(red[6],red[7])));
    __syncthreads();
    float ls = 0.f;
    for (int tau = tid; tau < TT; tau += NTHR) {
        float p = expf(es[tau] - bm);
        es[tau] = p;
        ls += p;
    }
    #pragma unroll
    for (int o = 16; o; o >>= 1) ls += __shfl_xor_sync(0xffffffffu, ls, o);
    if (l == 0) red[w] = ls;
    __syncthreads();
    float inv = 1.f/(red[0]+red[1]+red[2]+red[3]+red[4]+red[5]+red[6]+red[7]);
    float* arow = attns + ((size_t)t*NB + n)*TT;
    for (int tau = tid; tau < TT; tau += NTHR) {
        float a = es[tau] * inv;
        es[tau] = a;
        arow[tau] = a;
    }
    __syncthreads();

    // ctx = attn @ values
    {
        float4 acc = make_float4(0.f, 0.f, 0.f, 0.f);
        for (int tau = w; tau < len; tau += 8) {
            float a = es[tau];
            float4 v = ((const float4*)(values + ((size_t)tau*NB + n)*VD))[l];
            acc.x += a*v.x; acc.y += a*v.y; acc.z += a*v.z; acc.w += a*v.w;
        }
        *(float4*)&ctxp[w*VD + (l<<2)] = acc;
    }
    __syncthreads();
    if (tid < VD) {
        float s = 0.f;
        #pragma unroll
        for (int ww = 0; ww < 8; ++ww) s += ctxp[ww*VD + tid];
        g_ctx[n*VD + tid] = s;
        ctxv[tid] = s;
    }
    __syncthreads();

    // pred = (concat(h3,ctx) @ lin_W^T + lin_b) @ char_W^T + char_b
    if (tid < KD) {
        float m = lin_b[tid];
        #pragma unroll 4
        for (int k = 0; k < KD; ++k) m += h3s[k] * g_linWT[k*KD + tid];
        #pragma unroll 4
        for (int k = 0; k < VD; ++k) m += ctxv[k] * g_linWT[(KD+k)*KD + tid];
        mids[tid] = m;
    }
    __syncthreads();
    if (tid < VOC) {
        float p = charb[tid];
        #pragma unroll 4
        for (int k = 0; k < KD; ++k) p += mids[k] * charW[tid*KD + k];
        preds[((size_t)n*ML + t)*VOC + tid] = p;
    }
}

// ---------------- the single persistent kernel ----------------
__global__ void __launch_bounds__(NTHR, 2)
decoder_persistent(const float* __restrict__ keys, const float* __restrict__ values,
                   const int* __restrict__ seqlen, const int* __restrict__ text,
                   const float* __restrict__ embW,
                   const float* __restrict__ w_ih1, const float* __restrict__ w_hh1,
                   const float* __restrict__ b_ih1, const float* __restrict__ b_hh1,
                   const float* __restrict__ w_ih2, const float* __restrict__ w_hh2,
                   const float* __restrict__ b_ih2, const float* __restrict__ b_hh2,
                   const float* __restrict__ w_ih3, const float* __restrict__ w_hh3,
                   const float* __restrict__ b_ih3, const float* __restrict__ b_hh3,
                   const float* __restrict__ lin_W, const float* __restrict__ lin_b,
                   const float* __restrict__ char_W, const float* __restrict__ char_b,
                   float* __restrict__ preds, float* __restrict__ attns)
{
    __shared__ __align__(16) float s_mem[5760];   // 23 KB: max(GEMM, attention)
    const int gid = blockIdx.x*NTHR + threadIdx.x;
    const int GS = NCTA*NTHR;

    // ---- phase 0: prep ----
    for (int i = gid; i < ML*NB*(ED/4); i += GS) {
        int e4 = i & 63; int rem = i >> 6; int n = rem & 255; int tt = rem >> 8;
        int ch = text[n*ML + tt];
        ((float4*)g_embs)[i] = ((const float4*)embW)[ch*(ED/4) + e4];
    }
    for (int i = gid; i < NB*HD; i += GS) {
        g_h1[0][i]=0.f; g_h1[1][i]=0.f; g_c1[i]=0.f;
        g_h2[0][i]=0.f; g_h2[1][i]=0.f; g_c2[i]=0.f;
    }
    for (int i = gid; i < NB*KD; i += GS) { g_h3[0][i]=0.f; g_h3[1][i]=0.f; g_c3[i]=0.f; }
    for (int i = gid; i < NB*VD; i += GS) g_ctx[i] = values[(size_t)(TT-1)*NB*VD + i];
    for (int i = gid; i < (KD+VD)*KD; i += GS) {
        int k = i >> 7, j = i & 127;
        g_linWT[i] = lin_W[j*(KD+VD) + k];
    }
    gridbar();

    // ---- 250 sequential steps ----
    for (int t = 0; t < ML; ++t) {
        const int p = t & 1;
        {
            Seg segs[3] = {
                { g_embs + (size_t)t*NB*ED, ED, w_ih1,      ED+VD, ED },
                { g_ctx,                    VD, w_ih1 + ED, ED+VD, VD },
                { g_h1[p],                  HD, w_hh1,      HD,    HD } };
            lstm_big(segs, 3, b_ih1, b_hh1, g_c1, g_h1[p^1], s_mem);
        }
        gridbar();
        {
            Seg segs[2] = {
                { g_h1[p^1], HD, w_ih2, HD, HD },
                { g_h2[p],   HD, w_hh2, HD, HD } };
            lstm_big(segs, 2, b_ih2, b_hh2, g_c2, g_h2[p^1], s_mem);
        }
        gridbar();
        {
            Seg segs[2] = {
                { g_h2[p^1], HD, w_ih3, HD, HD },
                { g_h3[p],   KD, w_hh3, KD, KD } };
            lstm_small(segs, 2, b_ih3, b_hh3, g_c3, g_h3[p^1], s_mem);
        }
        gridbar();
        attn_phase(seqlen, keys, values, lin_b, char_W, char_b,
                   g_h3[p^1], preds, attns, t, s_mem);
        gridbar();
    }
}

// ---------------- host ----------------
extern "C" void kernel_launch(void* const* d_in, const int* in_sizes, int n_in,
                              void* d_out, int out_size) {
    (void)in_sizes; (void)n_in; (void)out_size;
    const float* keys   = (const float*)d_in[0];
    const float* values = (const float*)d_in[1];
    const int*   seqlen = (const int*)  d_in[2];
    const int*   text   = (const int*)  d_in[3];
    const float* embW   = (const float*)d_in[4];
    const float* w_ih1  = (const float*)d_in[5];
    const float* w_hh1  = (const float*)d_in[6];
    const float* b_ih1  = (const float*)d_in[7];
    const float* b_hh1  = (const float*)d_in[8];
    const float* w_ih2  = (const float*)d_in[9];
    const float* w_hh2  = (const float*)d_in[10];
    const float* b_ih2  = (const float*)d_in[11];
    const float* b_hh2  = (const float*)d_in[12];
    const float* w_ih3  = (const float*)d_in[13];
    const float* w_hh3  = (const float*)d_in[14];
    const float* b_ih3  = (const float*)d_in[15];
    const float* b_hh3  = (const float*)d_in[16];
    const float* lin_W  = (const float*)d_in[17];
    const float* lin_b  = (const float*)d_in[18];
    const float* char_W = (const float*)d_in[19];
    const float* char_b = (const float*)d_in[20];

    float* preds = (float*)d_out;
    float* attns = preds + (size_t)NB*ML*VOC;

    decoder_persistent<<<NCTA, NTHR>>>(
        keys, values, seqlen, text, embW,
        w_ih1, w_hh1, b_ih1, b_hh1,
        w_ih2, w_hh2, b_ih2, b_hh2,
        w_ih3, w_hh3, b_ih3, b_hh3,
        lin_W, lin_b, char_W, char_b,
        preds, attns);
}

// round 7
// speedup vs baseline: 1.3752x; 1.3752x over previous
#include <cuda_runtime.h>
#include <math.h>

#define NB 256      // batch N
#define TT 1000     // attention length T
#define KD 128      // KS
#define VD 128      // VS
#define ED 256      // EMB
#define HD 512      // HID
#define ML 250      // MAXLEN
#define VOC 30
#define NCTA 256
#define NTHR 256

// ---------------- scratch (device globals: allocation-free) ----------------
__device__ __align__(16) float g_embs[(size_t)ML*NB*ED];   // (t,n,e)
__device__ __align__(16) float g_h1[2][NB*HD];
__device__ __align__(16) float g_h2[2][NB*HD];
__device__ __align__(16) float g_h3[2][NB*KD];
__device__ __align__(16) float g_c1[NB*HD];
__device__ __align__(16) float g_c2[NB*HD];
__device__ __align__(16) float g_c3[NB*KD];
__device__ __align__(16) float g_ctx[NB*VD];
__device__ __align__(16) float g_linWT[(KD+VD)*KD];        // [k][j]
__device__ unsigned g_bar;   // zero-initialized at module load; protocol restores 0
__device__ unsigned g_gen;

// ---------------- software grid barrier (launch-invariant) ----------------
__device__ __forceinline__ void gridbar() {
    __syncthreads();
    if (threadIdx.x == 0) {
        unsigned snap = *(volatile unsigned*)&g_gen;
        __threadfence();                       // release my CTA's writes
        unsigned a = atomicAdd(&g_bar, 1u);
        if (a == NCTA - 1u) {
            g_bar = 0u;
            __threadfence();
            atomicAdd(&g_gen, 1u);
        } else {
            while (*(volatile unsigned*)&g_gen == snap) __nanosleep(64);
        }
        __threadfence();                       // acquire (L1 invalidate)
    }
    __syncthreads();
}

// ---------------- packed fp32x2 helpers ----------------
__device__ __forceinline__ unsigned long long packdup(float x) {
    unsigned long long r;
    asm("mov.b64 %0, {%1, %1};" : "=l"(r) : "r"(__float_as_uint(x)));
    return r;
}
__device__ __forceinline__ void ffma2(unsigned long long& d,
                                      unsigned long long a, unsigned long long b) {
    asm("fma.rn.f32x2 %0, %1, %2, %0;" : "+l"(d) : "l"(a), "l"(b));
}
__device__ __forceinline__ float2 unpack2(unsigned long long v) {
    unsigned lo, hi;
    asm("mov.b64 {%0, %1}, %2;" : "=r"(lo), "=r"(hi) : "l"(v));
    float2 f; f.x = __uint_as_float(lo); f.y = __uint_as_float(hi);
    return f;
}
__device__ __forceinline__ float sigf(float x) { return 1.f/(1.f + expf(-x)); }

struct Seg { const float* A; int lda; const float* W; int ldw; int K; };

// ---------------- LSTM phase: 4-gate fused GEMM + cell, BM=32 BN=32, Hout=512 ----
// smem: As padded stride 36 (32x32 tile), Ws stride 36 (4*32 k-rows x 32 j)
__device__ void lstm_big(const Seg* segs, int nseg,
                         const float* __restrict__ b_ih, const float* __restrict__ b_hh,
                         float* __restrict__ c, float* __restrict__ hnew,
                         float* s_mem)
{
    const int cta = blockIdx.x;
    if (cta >= 128) return;                     // 8 m-tiles x 16 j-tiles
    const int tid = threadIdx.x;
    const int Hout = HD;
    const int m0 = (cta >> 4) * 32;
    const int j0 = (cta & 15) * 32;
    float* As = s_mem;            // 32 k x 32 m, stride 36 -> 1152 floats
    float* Ws = s_mem + 1152;     // 128 k-rows x 32 j, stride 36 -> 4608 floats
    const int tx = tid & 15;      // j pair
    const int ty = tid >> 4;      // m pair
    unsigned long long acc2[4][2];
    #pragma unroll
    for (int g = 0; g < 4; ++g) { acc2[g][0] = 0ull; acc2[g][1] = 0ull; }

    for (int s = 0; s < nseg; ++s) {
        const float* A = segs[s].A; const float* W = segs[s].W;
        const int lda = segs[s].lda, ldw = segs[s].ldw, K = segs[s].K;
        for (int kb = 0; kb < K; kb += 32) {
            {   // A tile: 1024 floats, 1 float4/thread, stored transposed [k][m]
                int e = tid * 4;
                int row = e >> 5, col = e & 31;
                float4 v = *(const float4*)(A + (size_t)(m0+row)*lda + kb + col);
                As[(col+0)*36 + row] = v.x;
                As[(col+1)*36 + row] = v.y;
                As[(col+2)*36 + row] = v.z;
                As[(col+3)*36 + row] = v.w;
            }
            #pragma unroll
            for (int it = 0; it < 4; ++it) {    // W tiles: 4096 floats
                int e = (tid + it*256) * 4;
                int r = e >> 5, col = e & 31;
                int g = r >> 5, j = r & 31;
                float4 v = *(const float4*)(W + (size_t)(g*Hout + j0 + j)*ldw + kb + col);
                Ws[((g<<5) + col+0)*36 + j] = v.x;
                Ws[((g<<5) + col+1)*36 + j] = v.y;
                Ws[((g<<5) + col+2)*36 + j] = v.z;
                Ws[((g<<5) + col+3)*36 + j] = v.w;
            }
            __syncthreads();
            #pragma unroll
            for (int k = 0; k < 32; ++k) {
                float2 av = *(const float2*)&As[k*36 + ty*2];
                unsigned long long aa0 = packdup(av.x);
                unsigned long long aa1 = packdup(av.y);
                #pragma unroll
                for (int g = 0; g < 4; ++g) {
                    unsigned long long w2 =
                        *(const unsigned long long*)&Ws[((g<<5)+k)*36 + tx*2];
                    ffma2(acc2[g][0], w2, aa0);
                    ffma2(acc2[g][1], w2, aa1);
                }
            }
            __syncthreads();
        }
    }
    // fused cell epilogue
    #pragma unroll
    for (int i = 0; i < 2; ++i) {
        int m = m0 + ty*2 + i;
        float2 gi = unpack2(acc2[0][i]);
        float2 gf = unpack2(acc2[1][i]);
        float2 gg = unpack2(acc2[2][i]);
        float2 go = unpack2(acc2[3][i]);
        float gia[2] = {gi.x, gi.y}, gfa[2] = {gf.x, gf.y};
        float gga[2] = {gg.x, gg.y}, goa[2] = {go.x, go.y};
        #pragma unroll
        for (int jj = 0; jj < 2; ++jj) {
            int j = j0 + tx*2 + jj;
            float xi = gia[jj] + b_ih[0*HD + j] + b_hh[0*HD + j];
            float xf = gfa[jj] + b_ih[1*HD + j] + b_hh[1*HD + j];
            float xg = gga[jj] + b_ih[2*HD + j] + b_hh[2*HD + j];
            float xo = goa[jj] + b_ih[3*HD + j] + b_hh[3*HD + j];
            size_t idx = (size_t)m*HD + j;
            float cn = sigf(xf)*c[idx] + sigf(xi)*tanhf(xg);
            c[idx] = cn;
            hnew[idx] = sigf(xo)*tanhf(cn);
        }
    }
}

// ---------------- LSTM3 phase: BM=16 BN=16, Hout=128 ----------------
__device__ void lstm_small(const Seg* segs, int nseg,
                           const float* __restrict__ b_ih, const float* __restrict__ b_hh,
                           float* __restrict__ c, float* __restrict__ hnew,
                           float* s_mem)
{
    const int cta = blockIdx.x;
    if (cta >= 128) return;                     // 16 m-tiles x 8 j-tiles
    const int tid = threadIdx.x;
    const int Hout = KD;
    const int m0 = (cta >> 3) * 16;
    const int j0 = (cta & 7) * 16;
    float* As = s_mem;            // 32 k x 16 m, stride 36
    float* Ws = s_mem + 1152;     // 128 k-rows x 16 j, stride 20 -> 2560 floats
    const int tx = tid & 15;
    const int ty = tid >> 4;
    float acc[4] = {0.f, 0.f, 0.f, 0.f};

    for (int s = 0; s < nseg; ++s) {
        const float* A = segs[s].A; const float* W = segs[s].W;
        const int lda = segs[s].lda, ldw = segs[s].ldw, K = segs[s].K;
        for (int kb = 0; kb < K; kb += 32) {
            if (tid < 128) {                    // A tile: 512 floats
                int e = tid * 4;
                int row = e >> 5, col = e & 31;
                float4 v = *(const float4*)(A + (size_t)(m0+row)*lda + kb + col);
                As[(col+0)*36 + row] = v.x;
                As[(col+1)*36 + row] = v.y;
                As[(col+2)*36 + row] = v.z;
                As[(col+3)*36 + row] = v.w;
            }
            #pragma unroll
            for (int it = 0; it < 2; ++it) {    // W tiles: 2048 floats
                int e = (tid + it*256) * 4;
                int r = e >> 5, col = e & 31;
                int g = r >> 4, j = r & 15;
                float4 v = *(const float4*)(W + (size_t)(g*Hout + j0 + j)*ldw + kb + col);
                Ws[((g<<5) + col+0)*20 + j] = v.x;
                Ws[((g<<5) + col+1)*20 + j] = v.y;
                Ws[((g<<5) + col+2)*20 + j] = v.z;
                Ws[((g<<5) + col+3)*20 + j] = v.w;
            }
            __syncthreads();
            #pragma unroll
            for (int k = 0; k < 32; ++k) {
                float a = As[k*36 + ty];
                #pragma unroll
                for (int g = 0; g < 4; ++g)
                    acc[g] += Ws[((g<<5)+k)*20 + tx] * a;
            }
            __syncthreads();
        }
    }
    {
        int m = m0 + ty, j = j0 + tx;
        float xi = acc[0] + b_ih[0*KD + j] + b_hh[0*KD + j];
        float xf = acc[1] + b_ih[1*KD + j] + b_hh[1*KD + j];
        float xg = acc[2] + b_ih[2*KD + j] + b_hh[2*KD + j];
        float xo = acc[3] + b_ih[3*KD + j] + b_hh[3*KD + j];
        size_t idx = (size_t)m*KD + j;
        float cn = sigf(xf)*c[idx] + sigf(xi)*tanhf(xg);
        c[idx] = cn;
        hnew[idx] = sigf(xo)*tanhf(cn);
    }
}

// ---------------- attention + output head: one CTA per n ----------------
__device__ void attn_phase(const int* __restrict__ seqlen,
                           const float* __restrict__ keys,
                           const float* __restrict__ values,
                           const float* __restrict__ lin_b,
                           const float* __restrict__ charW,
                           const float* __restrict__ charb,
                           const float* __restrict__ h3,
                           float* __restrict__ preds,
                           float* __restrict__ attns,
                           int t, float* s_mem)
{
    float* h3s  = s_mem;          // 128
    float* es   = s_mem + 128;    // 1000
    float* ctxp = s_mem + 1128;   // 8*128
    float* ctxv = s_mem + 2152;   // 128
    float* mids = s_mem + 2280;   // 128
    float* red  = s_mem + 2408;   // 8

    int n = blockIdx.x;
    int tid = threadIdx.x;
    int w = tid >> 5, l = tid & 31;

    if (tid < KD) h3s[tid] = h3[n*KD + tid];
    int len = seqlen[n];
    if (len < 1) len = 1; if (len > TT) len = TT;
    __syncthreads();

    // energies: only tau < len read
    {
        int g = l >> 3, kq = l & 7;
        const float4* h34 = (const float4*)h3s;
        float4 hv[4];
        #pragma unroll
        for (int q = 0; q < 4; ++q) hv[q] = h34[kq + (q<<3)];
        int nIt = (len + 31) >> 5;
        for (int it = 0; it < nIt; ++it) {
            int tau = (it << 5) + (w << 2) + g;
            float p = 0.f;
            if (tau < len) {
                const float4* kp = (const float4*)(keys + ((size_t)tau*NB + n)*KD);
                #pragma unroll
                for (int q = 0; q < 4; ++q) {
                    float4 kv = kp[kq + (q<<3)];
                    p += kv.x*hv[q].x + kv.y*hv[q].y + kv.z*hv[q].z + kv.w*hv[q].w;
                }
            }
            p += __shfl_xor_sync(0xffffffffu, p, 4);
            p += __shfl_xor_sync(0xffffffffu, p, 2);
            p += __shfl_xor_sync(0xffffffffu, p, 1);
            if (kq == 0 && tau < len) es[tau] = p;
        }
    }
    __syncthreads();

    // masked softmax over TT
    float lm = -3.4e38f;
    for (int tau = tid; tau < TT; tau += NTHR) {
        float x = (tau < len) ? es[tau] : -1e9f;
        es[tau] = x;
        lm = fmaxf(lm, x);
    }
    #pragma unroll
    for (int o = 16; o; o >>= 1) lm = fmaxf(lm, __shfl_xor_sync(0xffffffffu, lm, o));
    if (l == 0) red[w] = lm;
    __syncthreads();
    float bm = fmaxf(fmaxf(fmaxf(red[0],red[1]), fmaxf(red[2],red[3])),
                     fmaxf(fmaxf(red[4],red[5]), fmaxf(red[6],red[7])));
    __syncthreads();
    float ls = 0.f;
    for (int tau = tid; tau < TT; tau += NTHR) {
        float p = expf(es[tau] - bm);
        es[tau] = p;
        ls += p;
    }
    #pragma unroll
    for (int o = 16; o; o >>= 1) ls += __shfl_xor_sync(0xffffffffu, ls, o);
    if (l == 0) red[w] = ls;
    __syncthreads();
    float inv = 1.f/(red[0]+red[1]+red[2]+red[3]+red[4]+red[5]+red[6]+red[7]);
    float* arow = attns + ((size_t)t*NB + n)*TT;
    for (int tau = tid; tau < TT; tau += NTHR) {
        float a = es[tau] * inv;
        es[tau] = a;
        arow[tau] = a;
    }
    __syncthreads();

    // ctx = attn @ values
    {
        float4 acc = make_float4(0.f, 0.f, 0.f, 0.f);
        for (int tau = w; tau < len; tau += 8) {
            float a = es[tau];
            float4 v = ((const float4*)(values + ((size_t)tau*NB + n)*VD))[l];
            acc.x += a*v.x; acc.y += a*v.y; acc.z += a*v.z; acc.w += a*v.w;
        }
        *(float4*)&ctxp[w*VD + (l<<2)] = acc;
    }
    __syncthreads();
    if (tid < VD) {
        float s = 0.f;
        #pragma unroll
        for (int ww = 0; ww < 8; ++ww) s += ctxp[ww*VD + tid];
        g_ctx[n*VD + tid] = s;
        ctxv[tid] = s;
    }
    __syncthreads();

    // pred = (concat(h3,ctx) @ lin_W^T + lin_b) @ char_W^T + char_b
    if (tid < KD) {
        float m = lin_b[tid];
        #pragma unroll 4
        for (int k = 0; k < KD; ++k) m += h3s[k] * g_linWT[k*KD + tid];
        #pragma unroll 4
        for (int k = 0; k < VD; ++k) m += ctxv[k] * g_linWT[(KD+k)*KD + tid];
        mids[tid] = m;
    }
    __syncthreads();
    if (tid < VOC) {
        float p = charb[tid];
        #pragma unroll 4
        for (int k = 0; k < KD; ++k) p += mids[k] * charW[tid*KD + k];
        preds[((size_t)n*ML + t)*VOC + tid] = p;
    }
}

// ---------------- the single persistent kernel ----------------
__global__ void __launch_bounds__(NTHR, 2)
decoder_persistent(const float* __restrict__ keys, const float* __restrict__ values,
                   const int* __restrict__ seqlen, const int* __restrict__ text,
                   const float* __restrict__ embW,
                   const float* __restrict__ w_ih1, const float* __restrict__ w_hh1,
                   const float* __restrict__ b_ih1, const float* __restrict__ b_hh1,
                   const float* __restrict__ w_ih2, const float* __restrict__ w_hh2,
                   const float* __restrict__ b_ih2, const float* __restrict__ b_hh2,
                   const float* __restrict__ w_ih3, const float* __restrict__ w_hh3,
                   const float* __restrict__ b_ih3, const float* __restrict__ b_hh3,
                   const float* __restrict__ lin_W, const float* __restrict__ lin_b,
                   const float* __restrict__ char_W, const float* __restrict__ char_b,
                   float* __restrict__ preds, float* __restrict__ attns)
{
    __shared__ __align__(16) float s_mem[5760];   // 23 KB: max(GEMM, attention)
    const int gid = blockIdx.x*NTHR + threadIdx.x;
    const int GS = NCTA*NTHR;

    // ---- phase 0: prep ----
    for (int i = gid; i < ML*NB*(ED/4); i += GS) {
        int e4 = i & 63; int rem = i >> 6; int n = rem & 255; int tt = rem >> 8;
        int ch = text[n*ML + tt];
        ((float4*)g_embs)[i] = ((const float4*)embW)[ch*(ED/4) + e4];
    }
    for (int i = gid; i < NB*HD; i += GS) {
        g_h1[0][i]=0.f; g_h1[1][i]=0.f; g_c1[i]=0.f;
        g_h2[0][i]=0.f; g_h2[1][i]=0.f; g_c2[i]=0.f;
    }
    for (int i = gid; i < NB*KD; i += GS) { g_h3[0][i]=0.f; g_h3[1][i]=0.f; g_c3[i]=0.f; }
    for (int i = gid; i < NB*VD; i += GS) g_ctx[i] = values[(size_t)(TT-1)*NB*VD + i];
    for (int i = gid; i < (KD+VD)*KD; i += GS) {
        int k = i >> 7, j = i & 127;
        g_linWT[i] = lin_W[j*(KD+VD) + k];
    }
    gridbar();

    // ---- 250 sequential steps ----
    for (int t = 0; t < ML; ++t) {
        const int p = t & 1;
        {
            Seg segs[3] = {
                { g_embs + (size_t)t*NB*ED, ED, w_ih1,      ED+VD, ED },
                { g_ctx,                    VD, w_ih1 + ED, ED+VD, VD },
                { g_h1[p],                  HD, w_hh1,      HD,    HD } };
            lstm_big(segs, 3, b_ih1, b_hh1, g_c1, g_h1[p^1], s_mem);
        }
        gridbar();
        {
            Seg segs[2] = {
                { g_h1[p^1], HD, w_ih2, HD, HD },
                { g_h2[p],   HD, w_hh2, HD, HD } };
            lstm_big(segs, 2, b_ih2, b_hh2, g_c2, g_h2[p^1], s_mem);
        }
        gridbar();
        {
            Seg segs[2] = {
                { g_h2[p^1], HD, w_ih3, HD, HD },
                { g_h3[p],   KD, w_hh3, KD, KD } };
            lstm_small(segs, 2, b_ih3, b_hh3, g_c3, g_h3[p^1], s_mem);
        }
        gridbar();
        attn_phase(seqlen, keys, values, lin_b, char_W, char_b,
                   g_h3[p^1], preds, attns, t, s_mem);
        gridbar();
    }
}

// ---------------- host ----------------
extern "C" void kernel_launch(void* const* d_in, const int* in_sizes, int n_in,
                              void* d_out, int out_size) {
    (void)in_sizes; (void)n_in; (void)out_size;
    const float* keys   = (const float*)d_in[0];
    const float* values = (const float*)d_in[1];
    const int*   seqlen = (const int*)  d_in[2];
    const int*   text   = (const int*)  d_in[3];
    const float* embW   = (const float*)d_in[4];
    const float* w_ih1  = (const float*)d_in[5];
    const float* w_hh1  = (const float*)d_in[6];
    const float* b_ih1  = (const float*)d_in[7];
    const float* b_hh1  = (const float*)d_in[8];
    const float* w_ih2  = (const float*)d_in[9];
    const float* w_hh2  = (const float*)d_in[10];
    const float* b_ih2  = (const float*)d_in[11];
    const float* b_hh2  = (const float*)d_in[12];
    const float* w_ih3  = (const float*)d_in[13];
    const float* w_hh3  = (const float*)d_in[14];
    const float* b_ih3  = (const float*)d_in[15];
    const float* b_hh3  = (const float*)d_in[16];
    const float* lin_W  = (const float*)d_in[17];
    const float* lin_b  = (const float*)d_in[18];
    const float* char_W = (const float*)d_in[19];
    const float* char_b = (const float*)d_in[20];

    float* preds = (float*)d_out;
    float* attns = preds + (size_t)NB*ML*VOC;

    decoder_persistent<<<NCTA, NTHR>>>(
        keys, values, seqlen, text, embW,
        w_ih1, w_hh1, b_ih1, b_hh1,
        w_ih2, w_hh2, b_ih2, b_hh2,
        w_ih3, w_hh3, b_ih3, b_hh3,
        lin_W, lin_b, char_W, char_b,
        preds, attns);
}

// round 8
// speedup vs baseline: 2.6536x; 1.9297x over previous
#include <cuda_runtime.h>
#include <math.h>

#define NB 256
#define TT 1000
#define KD 128
#define VD 128
#define ED 256
#define HD 512
#define ML 250
#define VOC 30
#define NCTA 256
#define NTHR 256
#define SPL 8
#define PS ((size_t)256*2048)

__device__ __align__(16) float g_embs[(size_t)ML*NB*ED];
__device__ __align__(16) float g_h1[NB*HD], g_c1[NB*HD];
__device__ __align__(16) float g_h2[NB*HD], g_c2[NB*HD];
__device__ __align__(16) float g_h3[NB*KD], g_c3[NB*KD];
__device__ __align__(16) float g_ctx[NB*VD];
__device__ __align__(16) float g_linWT[(KD+VD)*KD];
__device__ __align__(16) float g_part[SPL*PS];
__device__ unsigned g_bar, g_gen;

__device__ __forceinline__ void gridbar() {
    __syncthreads();
    if (threadIdx.x == 0) {
        unsigned snap = *(volatile unsigned*)&g_gen;
        __threadfence();
        unsigned a = atomicAdd(&g_bar, 1u);
        if (a == NCTA - 1u) {
            g_bar = 0u;
            __threadfence();
            atomicAdd(&g_gen, 1u);
        } else {
            while (*(volatile unsigned*)&g_gen == snap) __nanosleep(32);
        }
        __threadfence();
    }
    __syncthreads();
}

__device__ __forceinline__ unsigned long long packdup(float x) {
    unsigned long long r;
    asm("mov.b64 %0, {%1, %1};" : "=l"(r) : "r"(__float_as_uint(x)));
    return r;
}
__device__ __forceinline__ void ffma2(unsigned long long& d,
                                      unsigned long long a, unsigned long long b) {
    asm("fma.rn.f32x2 %0, %1, %2, %0;" : "+l"(d) : "l"(a), "l"(b));
}
__device__ __forceinline__ float2 unpack2(unsigned long long v) {
    unsigned lo, hi;
    asm("mov.b64 {%0, %1}, %2;" : "=r"(lo), "=r"(hi) : "l"(v));
    float2 f; f.x = __uint_as_float(lo); f.y = __uint_as_float(hi);
    return f;
}
__device__ __forceinline__ float sigf(float x) { return 1.f/(1.f + expf(-x)); }

struct Seg { const float* A; int lda; const float* W; int ldw; int K; };

// ---- split-K GEMM: partial[s] = A @ W^T ; BM=128, BN=16*TN, per-thread 8xTN ----
template<int TN>
__device__ void gemm_phase(const Seg* segs, int nseg, int H, int Ktot, float* s_mem)
{
    const int BN = 16*TN;
    const int Ncols = 4*H;
    const int nt = Ncols / BN;
    const int tiles = 2*nt;
    const int cta = blockIdx.x;
    if (cta >= tiles*SPL) return;
    const int s  = cta / tiles;
    const int rem = cta - s*tiles;
    const int m0 = (rem / nt) * 128;
    const int j0 = (rem % nt) * BN;
    const int nbt = Ktot >> 5;
    const int b0 = (nbt*s)/SPL, b1 = (nbt*(s+1))/SPL;

    float* As = s_mem;                 // [32][132] transposed A tile
    float* Ws = s_mem + 32*132;        // [32][BN+4] permuted W tile
    const int WSS = BN + 4;
    const int tid = threadIdx.x;
    const int tx = tid & 15, ty = tid >> 4;

    unsigned long long acc[8][TN/2];
    #pragma unroll
    for (int i = 0; i < 8; ++i)
        #pragma unroll
        for (int jp = 0; jp < TN/2; ++jp) acc[i][jp] = 0ull;

    for (int b = b0; b < b1; ++b) {
        const int kb = b << 5;
        const float *Ap = segs[0].A, *Wp = segs[0].W;
        int la = segs[0].lda, lw = segs[0].ldw;
        {
            int base = 0;
            for (int q = 0; q < nseg; ++q) {
                if (kb >= base && kb < base + segs[q].K) {
                    Ap = segs[q].A + (kb - base); la = segs[q].lda;
                    Wp = segs[q].W + (kb - base); lw = segs[q].ldw;
                }
                base += segs[q].K;
            }
        }
        __syncthreads();
        #pragma unroll
        for (int it = 0; it < 4; ++it) {      // A tile 128x32
            int q = tid + (it << 8); int m = q >> 3, kq = q & 7;
            float4 v = *(const float4*)(Ap + (size_t)(m0+m)*la + (kq << 2));
            As[(kq*4+0)*132 + m] = v.x;
            As[(kq*4+1)*132 + m] = v.y;
            As[(kq*4+2)*132 + m] = v.z;
            As[(kq*4+3)*132 + m] = v.w;
        }
        #pragma unroll
        for (int it = 0; it < BN/32; ++it) {  // W tile BNx32
            int q = tid + (it << 8); int j = q >> 3, kq = q & 7;
            float4 v = *(const float4*)(Wp + (size_t)(j0+j)*lw + (kq << 2));
            int pos;
            if (TN == 8) { int g = j >> 3, r = j & 7; pos = (r < 4) ? g*4 + r : 64 + g*4 + (r-4); }
            else pos = j;
            Ws[(kq*4+0)*WSS + pos] = v.x;
            Ws[(kq*4+1)*WSS + pos] = v.y;
            Ws[(kq*4+2)*WSS + pos] = v.z;
            Ws[(kq*4+3)*WSS + pos] = v.w;
        }
        __syncthreads();
        #pragma unroll 8
        for (int k = 0; k < 32; ++k) {
            float4 a0 = *(const float4*)&As[k*132 + ty*8];
            float4 a1 = *(const float4*)&As[k*132 + ty*8 + 4];
            unsigned long long da[8];
            da[0]=packdup(a0.x); da[1]=packdup(a0.y); da[2]=packdup(a0.z); da[3]=packdup(a0.w);
            da[4]=packdup(a1.x); da[5]=packdup(a1.y); da[6]=packdup(a1.z); da[7]=packdup(a1.w);
            float4 w0 = *(const float4*)&Ws[k*WSS + tx*4];
            const unsigned long long* wp = (const unsigned long long*)&w0;
            if (TN == 8) {
                float4 w1 = *(const float4*)&Ws[k*WSS + 64 + tx*4];
                const unsigned long long* wq = (const unsigned long long*)&w1;
                #pragma unroll
                for (int i = 0; i < 8; ++i) {
                    ffma2(acc[i][0], wp[0], da[i]);
                    ffma2(acc[i][1], wp[1], da[i]);
                    ffma2(acc[i][2], wq[0], da[i]);
                    ffma2(acc[i][3], wq[1], da[i]);
                }
            } else {
                #pragma unroll
                for (int i = 0; i < 8; ++i) {
                    ffma2(acc[i][0], wp[0], da[i]);
                    ffma2(acc[i][1], wp[1], da[i]);
                }
            }
        }
    }
    float* dst = g_part + (size_t)s*PS;
    #pragma unroll
    for (int i = 0; i < 8; ++i) {
        int m = m0 + ty*8 + i;
        if (TN == 8) {
            int j = j0 + tx*8;
            float2 v0 = unpack2(acc[i][0]), v1 = unpack2(acc[i][1]);
            float2 v2 = unpack2(acc[i][2]), v3 = unpack2(acc[i][3]);
            *(float4*)&dst[(size_t)m*Ncols + j]     = make_float4(v0.x, v0.y, v1.x, v1.y);
            *(float4*)&dst[(size_t)m*Ncols + j + 4] = make_float4(v2.x, v2.y, v3.x, v3.y);
        } else {
            int j = j0 + tx*4;
            float2 v0 = unpack2(acc[i][0]), v1 = unpack2(acc[i][1]);
            *(float4*)&dst[(size_t)m*Ncols + j] = make_float4(v0.x, v0.y, v1.x, v1.y);
        }
    }
}

// ---- cell phase: gates = sum partials + biases -> LSTM update ----
__device__ void cell_phase(int H, const float* __restrict__ b_ih,
                           const float* __restrict__ b_hh,
                           float* __restrict__ hst, float* __restrict__ cst)
{
    const int Ncols = 4*H;
    const int gid = blockIdx.x*NTHR + threadIdx.x;
    const int hq = H >> 2;
    for (int q = gid; q < NB*hq; q += NCTA*NTHR) {
        int n = q / hq, j = (q - n*hq) << 2;
        float4 gs[4];
        #pragma unroll
        for (int g = 0; g < 4; ++g) {
            size_t off = (size_t)n*Ncols + g*H + j;
            float4 a = *(const float4*)&g_part[off];
            #pragma unroll
            for (int sp = 1; sp < SPL; ++sp) {
                float4 p = *(const float4*)&g_part[(size_t)sp*PS + off];
                a.x += p.x; a.y += p.y; a.z += p.z; a.w += p.w;
            }
            float4 bi = *(const float4*)&b_ih[g*H + j];
            float4 bh = *(const float4*)&b_hh[g*H + j];
            a.x += bi.x + bh.x; a.y += bi.y + bh.y;
            a.z += bi.z + bh.z; a.w += bi.w + bh.w;
            gs[g] = a;
        }
        size_t idx = (size_t)n*H + j;
        float4 cv = *(const float4*)&cst[idx];
        float hn[4], cn[4];
        const float* fi = (const float*)&gs[0];
        const float* ff = (const float*)&gs[1];
        const float* fg = (const float*)&gs[2];
        const float* fo = (const float*)&gs[3];
        const float* pc = (const float*)&cv;
        #pragma unroll
        for (int c = 0; c < 4; ++c) {
            float nc = sigf(ff[c])*pc[c] + sigf(fi[c])*tanhf(fg[c]);
            cn[c] = nc;
            hn[c] = sigf(fo[c])*tanhf(nc);
        }
        *(float4*)&cst[idx] = *(float4*)cn;
        *(float4*)&hst[idx] = *(float4*)hn;
    }
}

// ---- attention + cell3 + output head: one CTA per n ----
__device__ void attn_phase(const int* __restrict__ seqlen,
                           const float* __restrict__ keys,
                           const float* __restrict__ values,
                           const float* __restrict__ b_ih3,
                           const float* __restrict__ b_hh3,
                           const float* __restrict__ lin_b,
                           const float* __restrict__ charW,
                           const float* __restrict__ charb,
                           float* __restrict__ preds,
                           float* __restrict__ attns,
                           int t, float* s_mem)
{
    float* h3s  = s_mem;          // 128
    float* es   = s_mem + 128;    // 1000
    float* ctxp = s_mem + 1128;   // 8*128
    float* ctxv = s_mem + 2152;   // 128
    float* mids = s_mem + 2280;   // 128
    float* red  = s_mem + 2408;   // 8

    const int n = blockIdx.x;
    const int tid = threadIdx.x;
    const int w = tid >> 5, l = tid & 31;

    if (tid < KD) {   // cell3 from LSTM3 partials (Ncols = 512)
        int j = tid;
        float g4[4];
        #pragma unroll
        for (int g = 0; g < 4; ++g) {
            size_t off = (size_t)n*512 + g*KD + j;
            float a = g_part[off];
            #pragma unroll
            for (int sp = 1; sp < SPL; ++sp) a += g_part[(size_t)sp*PS + off];
            g4[g] = a + b_ih3[g*KD + j] + b_hh3[g*KD + j];
        }
        size_t idx = (size_t)n*KD + j;
        float cn = sigf(g4[1])*g_c3[idx] + sigf(g4[0])*tanhf(g4[2]);
        g_c3[idx] = cn;
        float hv = sigf(g4[3])*tanhf(cn);
        g_h3[idx] = hv;
        h3s[j] = hv;
    }
    int len = seqlen[n];
    if (len < 1) len = 1; if (len > TT) len = TT;
    __syncthreads();

    {   // energies, tau < len only
        int g = l >> 3, kq = l & 7;
        const float4* h34 = (const float4*)h3s;
        float4 hv[4];
        #pragma unroll
        for (int q = 0; q < 4; ++q) hv[q] = h34[kq + (q<<3)];
        int nIt = (len + 31) >> 5;
        for (int it = 0; it < nIt; ++it) {
            int tau = (it << 5) + (w << 2) + g;
            float p = 0.f;
            if (tau < len) {
                const float4* kp = (const float4*)(keys + ((size_t)tau*NB + n)*KD);
                #pragma unroll
                for (int q = 0; q < 4; ++q) {
                    float4 kv = kp[kq + (q<<3)];
                    p += kv.x*hv[q].x + kv.y*hv[q].y + kv.z*hv[q].z + kv.w*hv[q].w;
                }
            }
            p += __shfl_xor_sync(0xffffffffu, p, 4);
            p += __shfl_xor_sync(0xffffffffu, p, 2);
            p += __shfl_xor_sync(0xffffffffu, p, 1);
            if (kq == 0 && tau < len) es[tau] = p;
        }
    }
    __syncthreads();

    float lm = -3.4e38f;
    for (int tau = tid; tau < TT; tau += NTHR) {
        float x = (tau < len) ? es[tau] : -1e9f;
        es[tau] = x;
        lm = fmaxf(lm, x);
    }
    #pragma unroll
    for (int o = 16; o; o >>= 1) lm = fmaxf(lm, __shfl_xor_sync(0xffffffffu, lm, o));
    if (l == 0) red[w] = lm;
    __syncthreads();
    float bm = fmaxf(fmaxf(fmaxf(red[0],red[1]), fmaxf(red[2],red[3])),
                     fmaxf(fmaxf(red[4],red[5]), fmaxf(red[6],red[7])));
    __syncthreads();
    float ls = 0.f;
    for (int tau = tid; tau < TT; tau += NTHR) {
        float p = expf(es[tau] - bm);
        es[tau] = p;
        ls += p;
    }
    #pragma unroll
    for (int o = 16; o; o >>= 1) ls += __shfl_xor_sync(0xffffffffu, ls, o);
    if (l == 0) red[w] = ls;
    __syncthreads();
    float inv = 1.f/(red[0]+red[1]+red[2]+red[3]+red[4]+red[5]+red[6]+red[7]);
    float* arow = attns + ((size_t)t*NB + n)*TT;
    for (int tau = tid; tau < TT; tau += NTHR) {
        float a = es[tau] * inv;
        es[tau] = a;
        arow[tau] = a;
    }
    __syncthreads();

    {   // ctx = attn @ values
        float4 acc = make_float4(0.f, 0.f, 0.f, 0.f);
        for (int tau = w; tau < len; tau += 8) {
            float a = es[tau];
            float4 v = ((const float4*)(values + ((size_t)tau*NB + n)*VD))[l];
            acc.x += a*v.x; acc.y += a*v.y; acc.z += a*v.z; acc.w += a*v.w;
        }
        *(float4*)&ctxp[w*VD + (l<<2)] = acc;
    }
    __syncthreads();
    if (tid < VD) {
        float s = 0.f;
        #pragma unroll
        for (int ww = 0; ww < 8; ++ww) s += ctxp[ww*VD + tid];
        g_ctx[n*VD + tid] = s;
        ctxv[tid] = s;
    }
    __syncthreads();

    if (tid < KD) {
        float m = lin_b[tid];
        #pragma unroll 4
        for (int k = 0; k < KD; ++k) m += h3s[k] * g_linWT[k*KD + tid];
        #pragma unroll 4
        for (int k = 0; k < VD; ++k) m += ctxv[k] * g_linWT[(KD+k)*KD + tid];
        mids[tid] = m;
    }
    __syncthreads();
    if (tid < VOC) {
        float p = charb[tid];
        #pragma unroll 4
        for (int k = 0; k < KD; ++k) p += mids[k] * charW[tid*KD + k];
        preds[((size_t)n*ML + t)*VOC + tid] = p;
    }
}

// ---- single persistent kernel ----
__global__ void __launch_bounds__(NTHR, 2)
decoder_persistent(const float* __restrict__ keys, const float* __restrict__ values,
                   const int* __restrict__ seqlen, const int* __restrict__ text,
                   const float* __restrict__ embW,
                   const float* __restrict__ w_ih1, const float* __restrict__ w_hh1,
                   const float* __restrict__ b_ih1, const float* __restrict__ b_hh1,
                   const float* __restrict__ w_ih2, const float* __restrict__ w_hh2,
                   const float* __restrict__ b_ih2, const float* __restrict__ b_hh2,
                   const float* __restrict__ w_ih3, const float* __restrict__ w_hh3,
                   const float* __restrict__ b_ih3, const float* __restrict__ b_hh3,
                   const float* __restrict__ lin_W, const float* __restrict__ lin_b,
                   const float* __restrict__ char_W, const float* __restrict__ char_b,
                   float* __restrict__ preds, float* __restrict__ attns)
{
    __shared__ __align__(16) float s_mem[32*132 + 32*132];   // 33.8 KB
    const int gid = blockIdx.x*NTHR + threadIdx.x;
    const int GS = NCTA*NTHR;

    for (int i = gid; i < ML*NB*(ED/4); i += GS) {
        int e4 = i & 63; int rem = i >> 6; int n = rem & 255; int tt = rem >> 8;
        int ch = text[n*ML + tt];
        ((float4*)g_embs)[i] = ((const float4*)embW)[ch*(ED/4) + e4];
    }
    for (int i = gid; i < NB*HD; i += GS) {
        g_h1[i] = 0.f; g_c1[i] = 0.f; g_h2[i] = 0.f; g_c2[i] = 0.f;
    }
    for (int i = gid; i < NB*KD; i += GS) { g_h3[i] = 0.f; g_c3[i] = 0.f; }
    for (int i = gid; i < NB*VD; i += GS) g_ctx[i] = values[(size_t)(TT-1)*NB*VD + i];
    for (int i = gid; i < (KD+VD)*KD; i += GS) {
        int k = i >> 7, j = i & 127;
        g_linWT[i] = lin_W[j*(KD+VD) + k];
    }
    gridbar();

    for (int t = 0; t < ML; ++t) {
        {   // LSTM1: K = 256 + 128 + 512
            Seg segs[3] = {
                { g_embs + (size_t)t*NB*ED, ED, w_ih1,      ED+VD, ED },
                { g_ctx,                    VD, w_ih1 + ED, ED+VD, VD },
                { g_h1,                     HD, w_hh1,      HD,    HD } };
            gemm_phase<8>(segs, 3, HD, ED+VD+HD, s_mem);
        }
        gridbar();
        cell_phase(HD, b_ih1, b_hh1, g_h1, g_c1);
        gridbar();
        {   // LSTM2: K = 512 + 512
            Seg segs[2] = {
                { g_h1, HD, w_ih2, HD, HD },
                { g_h2, HD, w_hh2, HD, HD } };
            gemm_phase<8>(segs, 2, HD, 2*HD, s_mem);
        }
        gridbar();
        cell_phase(HD, b_ih2, b_hh2, g_h2, g_c2);
        gridbar();
        {   // LSTM3: K = 512 + 128, Hout = 128
            Seg segs[2] = {
                { g_h2, HD, w_ih3, HD, HD },
                { g_h3, KD, w_hh3, KD, KD } };
            gemm_phase<4>(segs, 2, KD, HD+KD, s_mem);
        }
        gridbar();
        attn_phase(seqlen, keys, values, b_ih3, b_hh3, lin_b, char_W, char_b,
                   preds, attns, t, s_mem);
        gridbar();
    }
}

// ---- host ----
extern "C" void kernel_launch(void* const* d_in, const int* in_sizes, int n_in,
                              void* d_out, int out_size) {
    (void)in_sizes; (void)n_in; (void)out_size;
    const float* keys   = (const float*)d_in[0];
    const float* values = (const float*)d_in[1];
    const int*   seqlen = (const int*)  d_in[2];
    const int*   text   = (const int*)  d_in[3];
    const float* embW   = (const float*)d_in[4];
    const float* w_ih1  = (const float*)d_in[5];
    const float* w_hh1  = (const float*)d_in[6];
    const float* b_ih1  = (const float*)d_in[7];
    const float* b_hh1  = (const float*)d_in[8];
    const float* w_ih2  = (const float*)d_in[9];
    const float* w_hh2  = (const float*)d_in[10];
    const float* b_ih2  = (const float*)d_in[11];
    const float* b_hh2  = (const float*)d_in[12];
    const float* w_ih3  = (const float*)d_in[13];
    const float* w_hh3  = (const float*)d_in[14];
    const float* b_ih3  = (const float*)d_in[15];
    const float* b_hh3  = (const float*)d_in[16];
    const float* lin_W  = (const float*)d_in[17];
    const float* lin_b  = (const float*)d_in[18];
    const float* char_W = (const float*)d_in[19];
    const float* char_b = (const float*)d_in[20];

    float* preds = (float*)d_out;
    float* attns = preds + (size_t)NB*ML*VOC;

    decoder_persistent<<<NCTA, NTHR>>>(
        keys, values, seqlen, text, embW,
        w_ih1, w_hh1, b_ih1, b_hh1,
        w_ih2, w_hh2, b_ih2, b_hh2,
        w_ih3, w_hh3, b_ih3, b_hh3,
        lin_W, lin_b, char_W, char_b,
        preds, attns);
}